// round 4
// baseline (speedup 1.0000x reference)
#include <cuda_runtime.h>
#include <math.h>

// Problem dims
#define T_STEPS 1024
#define D_DIM   2048
#define NHID    2048
#define NCATS   1000

// Recurrence kernel config
#define GBLK    148        // persistent blocks (<= SM count on B300/GB300)
#define PAIRS   14         // (Uz,Uh) row pairs per block; 148*14 = 2072 >= 2048
#define RTPB    448        // 14 warps: warp w owns pair w

// ---------------- device scratch (no allocations allowed) ----------------
__device__ float    g_xz[T_STEPS * NHID];   // x @ Wz.T
__device__ float    g_xh[T_STEPS * NHID];   // x @ Wh.T
__device__ float    g_hp[2][NHID];          // double-buffered hprev
__device__ float    g_logits[NCATS];
__device__ unsigned g_count = 0;
__device__ unsigned g_epoch = 0;

// ---------------- grid barrier (hand-rolled, capture-safe) ----------------
__device__ __forceinline__ void gbar(unsigned target) {
    __syncthreads();
    if (threadIdx.x == 0) {
        __threadfence();
        unsigned t = atomicAdd(&g_count, 1u);
        if (t == GBLK - 1) {
            atomicExch(&g_count, 0u);
            __threadfence();
            atomicExch(&g_epoch, target);
        } else {
            while (*(volatile unsigned*)&g_epoch < target) { __nanosleep(32); }
            __threadfence();
        }
    }
    __syncthreads();
}

// ---------------- fused input projections: g_xz = x@Wz.T, g_xh = x@Wh.T ---
// C[m,n] = sum_k A[m,k] * W[n,k]; A=[1024,2048], W=[2048,2048], both K-major.
#define BM 128
#define BN 128
#define BK 16

__global__ __launch_bounds__(256, 2)
void gemm_xw_kernel(const float* __restrict__ x,
                    const float* __restrict__ Wz,
                    const float* __restrict__ Wh) {
    const float* W = (blockIdx.z == 0) ? Wz : Wh;
    float* C       = (blockIdx.z == 0) ? g_xz : g_xh;

    __shared__ float As[BK][BM];
    __shared__ float Bs[BK][BN];

    const int tid = threadIdx.x;
    const int m0  = blockIdx.y * BM;
    const int n0  = blockIdx.x * BN;
    const int tr  = tid >> 4;    // 0..15
    const int tc  = tid & 15;    // 0..15

    float acc[8][8];
#pragma unroll
    for (int i = 0; i < 8; i++)
#pragma unroll
        for (int j = 0; j < 8; j++) acc[i][j] = 0.0f;

    for (int k0 = 0; k0 < D_DIM; k0 += BK) {
        // load 128x16 tiles of A and W (512 float4 each; 2 per thread each)
#pragma unroll
        for (int r = 0; r < 2; r++) {
            int idx = tid + r * 256;      // 0..511
            int row = idx >> 2;
            int c4  = (idx & 3) << 2;
            float4 a = *(const float4*)(x + (size_t)(m0 + row) * D_DIM + k0 + c4);
            As[c4 + 0][row] = a.x; As[c4 + 1][row] = a.y;
            As[c4 + 2][row] = a.z; As[c4 + 3][row] = a.w;
            float4 b = *(const float4*)(W + (size_t)(n0 + row) * D_DIM + k0 + c4);
            Bs[c4 + 0][row] = b.x; Bs[c4 + 1][row] = b.y;
            Bs[c4 + 2][row] = b.z; Bs[c4 + 3][row] = b.w;
        }
        __syncthreads();
#pragma unroll
        for (int kk = 0; kk < BK; kk++) {
            float ra[8], rb[8];
            *(float4*)&ra[0] = *(const float4*)&As[kk][tr * 4];
            *(float4*)&ra[4] = *(const float4*)&As[kk][64 + tr * 4];
            *(float4*)&rb[0] = *(const float4*)&Bs[kk][tc * 4];
            *(float4*)&rb[4] = *(const float4*)&Bs[kk][64 + tc * 4];
#pragma unroll
            for (int i = 0; i < 8; i++)
#pragma unroll
                for (int j = 0; j < 8; j++)
                    acc[i][j] = fmaf(ra[i], rb[j], acc[i][j]);
        }
        __syncthreads();
    }

    // write back (rows/cols in 4+4 split halves)
#pragma unroll
    for (int hi = 0; hi < 2; hi++)
#pragma unroll
        for (int i = 0; i < 4; i++) {
            int row = m0 + hi * 64 + tr * 4 + i;
#pragma unroll
            for (int hj = 0; hj < 2; hj++) {
                float4 v;
                v.x = acc[hi * 4 + i][hj * 4 + 0];
                v.y = acc[hi * 4 + i][hj * 4 + 1];
                v.z = acc[hi * 4 + i][hj * 4 + 2];
                v.w = acc[hi * 4 + i][hj * 4 + 3];
                *(float4*)(C + (size_t)row * NHID + n0 + hj * 64 + tc * 4) = v;
            }
        }
}

// ---------------- persistent recurrence + classifier + softmax ------------
__global__ __launch_bounds__(RTPB, 1)
void recur_kernel(const float* __restrict__ Uz,
                  const float* __restrict__ Uh,
                  const float* __restrict__ bz,
                  const float* __restrict__ zt0,
                  const float* __restrict__ htilde0,
                  const float* __restrict__ hprev0,
                  const float* __restrict__ Wout,
                  float* __restrict__ out) {
    extern __shared__ float sU[];       // [PAIRS][2][NHID]
    const int b   = blockIdx.x;
    const int tid = threadIdx.x;
    const int w   = tid >> 5;
    const int l   = tid & 31;
    const int row = b * PAIRS + w;
    const bool active = (row < NHID);

    // epoch base (stable: no barrier runs until all blocks arrive)
    unsigned e0 = *(volatile unsigned*)&g_epoch;
    unsigned ec = 0;

    // one-time: load this block's 14 (Uz,Uh) row pairs into SMEM
    for (int p = 0; p < PAIRS; p++) {
        int r = b * PAIRS + p;
        if (r < NHID) {
            float4*       dz = (float4*)(sU + (size_t)p * 2 * NHID);
            float4*       dh = dz + NHID / 4;
            const float4* sz = (const float4*)(Uz + (size_t)r * NHID);
            const float4* sh = (const float4*)(Uh + (size_t)r * NHID);
            for (int i = tid; i < NHID / 4; i += RTPB) {
                dz[i] = sz[i];
                dh[i] = sh[i];
            }
        }
    }

    // init per-row carry state (kept uniform across the warp)
    float z_s = 0.f, ht_s = 0.f, h_s = 0.f, bzr = 0.f;
    if (active) {
        z_s  = zt0[row];
        ht_s = htilde0[row];
        h_s  = hprev0[row];
        bzr  = bz[row];
        if (l == 0) g_hp[0][row] = h_s;   // hp buffer 0 = hprev0
    }
    __syncthreads();
    gbar(e0 + (++ec));

    const float4* uzr = (const float4*)(sU + (size_t)w * 2 * NHID);
    const float4* uhr = uzr + NHID / 4;

    for (int t = 0; t < T_STEPS; t++) {
        // load full hp_t into registers (L2-coherent: other SMs wrote it)
        const float4* hpg = (const float4*)(g_hp[t & 1]);
        float4 hp[16];
#pragma unroll
        for (int j = 0; j < 16; j++)
            hp[j] = __ldcg(hpg + l + 32 * j);

        float xzv = 0.f, xhv = 0.f;
        if (active) {
            xzv = __ldg(&g_xz[(size_t)t * NHID + row]);
            xhv = __ldg(&g_xh[(size_t)t * NHID + row]);
        }

        // dual dot products from SMEM-resident U rows
        float dz0 = 0.f, dz1 = 0.f, dh0 = 0.f, dh1 = 0.f;
#pragma unroll
        for (int j = 0; j < 16; j += 2) {
            float4 a0 = uzr[l + 32 * j];
            float4 b0 = uhr[l + 32 * j];
            float4 h0v = hp[j];
            dz0 = fmaf(a0.x, h0v.x, dz0); dz0 = fmaf(a0.y, h0v.y, dz0);
            dz0 = fmaf(a0.z, h0v.z, dz0); dz0 = fmaf(a0.w, h0v.w, dz0);
            dh0 = fmaf(b0.x, h0v.x, dh0); dh0 = fmaf(b0.y, h0v.y, dh0);
            dh0 = fmaf(b0.z, h0v.z, dh0); dh0 = fmaf(b0.w, h0v.w, dh0);
            float4 a1 = uzr[l + 32 * (j + 1)];
            float4 b1 = uhr[l + 32 * (j + 1)];
            float4 h1v = hp[j + 1];
            dz1 = fmaf(a1.x, h1v.x, dz1); dz1 = fmaf(a1.y, h1v.y, dz1);
            dz1 = fmaf(a1.z, h1v.z, dz1); dz1 = fmaf(a1.w, h1v.w, dz1);
            dh1 = fmaf(b1.x, h1v.x, dh1); dh1 = fmaf(b1.y, h1v.y, dh1);
            dh1 = fmaf(b1.z, h1v.z, dh1); dh1 = fmaf(b1.w, h1v.w, dh1);
        }
        float dz = dz0 + dz1;
        float dh = dh0 + dh1;
#pragma unroll
        for (int o = 16; o > 0; o >>= 1) {
            dz += __shfl_xor_sync(0xffffffffu, dz, o);
            dh += __shfl_xor_sync(0xffffffffu, dh, o);
        }

        // gate math (reference update order: h uses STALE z/htilde)
        float z_new  = 1.0f / (1.0f + expf(-(xzv + dz + bzr)));
        float ht_new = tanhf(xhv + dh);
        float h_new  = (1.0f - z_s) * h_s + z_s * ht_s;

        if (active && l == 0) g_hp[(t + 1) & 1][row] = h_new;
        z_s = z_new; ht_s = ht_new; h_s = h_new;

        gbar(e0 + (++ec));
    }

    // final h_T lives in g_hp[0] (t=1023 wrote buffer (1023+1)&1 = 0)
    // logits: warp gw computes dot(Wout[gw], h_T)
    {
        int gw = b * PAIRS + w;
        if (gw < NCATS) {
            const float4* wo = (const float4*)(Wout + (size_t)gw * NHID);
            const float4* hf = (const float4*)(g_hp[0]);
            float s = 0.f;
#pragma unroll
            for (int j = 0; j < 16; j++) {
                float4 wv = __ldg(wo + l + 32 * j);
                float4 hv = __ldcg(hf + l + 32 * j);
                s = fmaf(wv.x, hv.x, s); s = fmaf(wv.y, hv.y, s);
                s = fmaf(wv.z, hv.z, s); s = fmaf(wv.w, hv.w, s);
            }
#pragma unroll
            for (int o = 16; o > 0; o >>= 1)
                s += __shfl_xor_sync(0xffffffffu, s, o);
            if (l == 0) g_logits[gw] = s;
        }
    }
    gbar(e0 + (++ec));

    // softmax over 1000 logits by block 0
    if (b == 0) {
        __shared__ float sred[32];
        // max
        float m = -1e30f;
        for (int c = tid; c < NCATS; c += RTPB)
            m = fmaxf(m, __ldcg(&g_logits[c]));
#pragma unroll
        for (int o = 16; o > 0; o >>= 1)
            m = fmaxf(m, __shfl_xor_sync(0xffffffffu, m, o));
        if (l == 0) sred[w] = m;
        __syncthreads();
        if (tid < 32) {
            float mm = (tid < RTPB / 32) ? sred[tid] : -1e30f;
#pragma unroll
            for (int o = 16; o > 0; o >>= 1)
                mm = fmaxf(mm, __shfl_xor_sync(0xffffffffu, mm, o));
            if (tid == 0) sred[0] = mm;
        }
        __syncthreads();
        float gmax = sred[0];
        __syncthreads();
        // sum
        float s = 0.f;
        for (int c = tid; c < NCATS; c += RTPB)
            s += expf(__ldcg(&g_logits[c]) - gmax);
#pragma unroll
        for (int o = 16; o > 0; o >>= 1)
            s += __shfl_xor_sync(0xffffffffu, s, o);
        if (l == 0) sred[w] = s;
        __syncthreads();
        if (tid < 32) {
            float ss = (tid < RTPB / 32) ? sred[tid] : 0.f;
#pragma unroll
            for (int o = 16; o > 0; o >>= 1)
                ss += __shfl_xor_sync(0xffffffffu, ss, o);
            if (tid == 0) sred[0] = ss;
        }
        __syncthreads();
        float inv = 1.0f / sred[0];
        for (int c = tid; c < NCATS; c += RTPB)
            out[c] = expf(__ldcg(&g_logits[c]) - gmax) * inv;
    }
}

// ---------------- launch ----------------
extern "C" void kernel_launch(void* const* d_in, const int* in_sizes, int n_in,
                              void* d_out, int out_size) {
    (void)in_sizes; (void)n_in; (void)out_size;
    const float* x    = (const float*)d_in[0];
    const float* Wh   = (const float*)d_in[1];
    const float* Wz   = (const float*)d_in[2];
    // d_in[3] = Wr : feeds only the dead rt gate -> skipped
    const float* Uh   = (const float*)d_in[4];
    const float* Uz   = (const float*)d_in[5];
    const float* bz   = (const float*)d_in[6];
    // d_in[7] = Ur, d_in[8] = br : dead
    const float* Wout = (const float*)d_in[9];
    // d_in[10] = h0 : dead (overwritten before first use)
    const float* zt0  = (const float*)d_in[11];
    const float* ht0  = (const float*)d_in[12];
    const float* hp0  = (const float*)d_in[13];
    float* out = (float*)d_out;

    const int smem = PAIRS * 2 * NHID * (int)sizeof(float);  // 229376 B
    cudaFuncSetAttribute(recur_kernel,
                         cudaFuncAttributeMaxDynamicSharedMemorySize, smem);

    dim3 ggrid(NHID / BN, T_STEPS / BM, 2);   // (16, 8, 2)
    gemm_xw_kernel<<<ggrid, 256>>>(x, Wz, Wh);
    recur_kernel<<<GBLK, RTPB, smem>>>(Uz, Uh, bz, zt0, ht0, hp0, Wout, out);
}

// round 11
// speedup vs baseline: 1.1349x; 1.1349x over previous
#include <cuda_runtime.h>
#include <math.h>

// Problem dims
#define T_STEPS 1024
#define D_DIM   2048
#define NHID    2048
#define NCATS   1000

// Recurrence kernel config: 148 persistent blocks, 7 warps/block,
// each warp owns 2 hidden rows (2 (Uz,Uh) pairs). 148*14 = 2072 >= 2048.
#define GBLK    148
#define WARPS   7
#define RTPB    (WARPS * 32)      // 224
#define RPB     14                // rows per block

// ---------------- device scratch (no allocations allowed) ----------------
__device__ float    g_xz[T_STEPS * NHID];   // x @ Wz.T
__device__ float    g_xh[T_STEPS * NHID];   // x @ Wh.T
__device__ float    g_hp[2][NHID];          // double-buffered hprev
__device__ float    g_logits[NCATS];
// Barrier state: 4 group counters 128B apart (distinct L2 lines), a root
// counter, and the single epoch word (R4-proven release mechanism).
__device__ unsigned g_cnt4[128];            // use [g*32], g in 0..3
__device__ unsigned g_rootpad[32];          // root at [0]
__device__ unsigned g_epochpad[32];         // epoch at [0]

// ---------------- grid barrier: hierarchical arrival, R4-proven release ---
// Arrival: block's thread 0 atomicAdds its group counter (148 = 4*37, so the
// 37th arrival of each epoch is detected by old % 37 == 36 on a monotone
// counter -- no resets). Last-of-group bumps the root; 4th root arrival
// atomicExch-es the epoch to `target`. Release: volatile poll + nanosleep,
// exactly the structure that passed in R4.
__device__ __forceinline__ void gbar(unsigned target, int bid) {
    __syncthreads();
    if (threadIdx.x == 0) {
        __threadfence();
        unsigned old = atomicAdd(&g_cnt4[(bid & 3) * 32], 1u);
        if (old % 37u == 36u) {                       // last arrival in group
            unsigned r = atomicAdd(&g_rootpad[0], 1u);
            if ((r & 3u) == 3u)                       // last group
                atomicExch(&g_epochpad[0], target);
        }
        while ((int)(*(volatile unsigned*)&g_epochpad[0] - target) < 0) {
            __nanosleep(32);
        }
        __threadfence();
    }
    __syncthreads();
}

// ---------------- fused input projections: g_xz = x@Wz.T, g_xh = x@Wh.T ---
#define BM 128
#define BN 128
#define BK 16

__global__ __launch_bounds__(256, 2)
void gemm_xw_kernel(const float* __restrict__ x,
                    const float* __restrict__ Wz,
                    const float* __restrict__ Wh) {
    const float* W = (blockIdx.z == 0) ? Wz : Wh;
    float* C       = (blockIdx.z == 0) ? g_xz : g_xh;

    __shared__ float As[BK][BM];
    __shared__ float Bs[BK][BN];

    const int tid = threadIdx.x;
    const int m0  = blockIdx.y * BM;
    const int n0  = blockIdx.x * BN;
    const int tr  = tid >> 4;
    const int tc  = tid & 15;

    float acc[8][8];
#pragma unroll
    for (int i = 0; i < 8; i++)
#pragma unroll
        for (int j = 0; j < 8; j++) acc[i][j] = 0.0f;

    for (int k0 = 0; k0 < D_DIM; k0 += BK) {
#pragma unroll
        for (int r = 0; r < 2; r++) {
            int idx = tid + r * 256;
            int row = idx >> 2;
            int c4  = (idx & 3) << 2;
            float4 a = *(const float4*)(x + (size_t)(m0 + row) * D_DIM + k0 + c4);
            As[c4 + 0][row] = a.x; As[c4 + 1][row] = a.y;
            As[c4 + 2][row] = a.z; As[c4 + 3][row] = a.w;
            float4 b = *(const float4*)(W + (size_t)(n0 + row) * D_DIM + k0 + c4);
            Bs[c4 + 0][row] = b.x; Bs[c4 + 1][row] = b.y;
            Bs[c4 + 2][row] = b.z; Bs[c4 + 3][row] = b.w;
        }
        __syncthreads();
#pragma unroll
        for (int kk = 0; kk < BK; kk++) {
            float ra[8], rb[8];
            *(float4*)&ra[0] = *(const float4*)&As[kk][tr * 4];
            *(float4*)&ra[4] = *(const float4*)&As[kk][64 + tr * 4];
            *(float4*)&rb[0] = *(const float4*)&Bs[kk][tc * 4];
            *(float4*)&rb[4] = *(const float4*)&Bs[kk][64 + tc * 4];
#pragma unroll
            for (int i = 0; i < 8; i++)
#pragma unroll
                for (int j = 0; j < 8; j++)
                    acc[i][j] = fmaf(ra[i], rb[j], acc[i][j]);
        }
        __syncthreads();
    }

#pragma unroll
    for (int hi = 0; hi < 2; hi++)
#pragma unroll
        for (int i = 0; i < 4; i++) {
            int row = m0 + hi * 64 + tr * 4 + i;
#pragma unroll
            for (int hj = 0; hj < 2; hj++) {
                float4 v;
                v.x = acc[hi * 4 + i][hj * 4 + 0];
                v.y = acc[hi * 4 + i][hj * 4 + 1];
                v.z = acc[hi * 4 + i][hj * 4 + 2];
                v.w = acc[hi * 4 + i][hj * 4 + 3];
                *(float4*)(C + (size_t)row * NHID + n0 + hj * 64 + tc * 4) = v;
            }
        }
}

// ---------------- persistent recurrence + classifier + softmax ------------
// SMEM: per warp w, 4 rows of 2048 floats: [Uz[r0] | Uh[r0] | Uz[r1] | Uh[r1]]
__global__ __launch_bounds__(RTPB, 1)
void recur_kernel(const float* __restrict__ Uz,
                  const float* __restrict__ Uh,
                  const float* __restrict__ bz,
                  const float* __restrict__ zt0,
                  const float* __restrict__ htilde0,
                  const float* __restrict__ hprev0,
                  const float* __restrict__ Wout,
                  float* __restrict__ out) {
    extern __shared__ float sU[];       // [WARPS][4][NHID] = 229376 B

    const int b   = blockIdx.x;
    const int tid = threadIdx.x;
    const int w   = tid >> 5;
    const int l   = tid & 31;
    const int r0  = b * RPB + 2 * w;    // warp's first row; r0+1 is the second

    // Epoch base: every thread reads BEFORE its block's first arrival; no
    // release can happen until all blocks arrive, so this is race-free and
    // equal across blocks (R4-proven pattern).
    unsigned e0 = *(volatile unsigned*)&g_epochpad[0];
    unsigned ec = 0;

    // one-time: load this block's 14 (Uz,Uh) row pairs into SMEM.
    // Pair p -> warp p>>1, slots (p&1)*2 and (p&1)*2+1.
    for (int p = 0; p < RPB; p++) {
        int r = b * RPB + p;
        if (r < NHID) {
            float4*       dz = (float4*)(sU + ((size_t)(p >> 1) * 4 + (p & 1) * 2) * NHID);
            float4*       dh = dz + NHID / 4;
            const float4* szp = (const float4*)(Uz + (size_t)r * NHID);
            const float4* shp = (const float4*)(Uh + (size_t)r * NHID);
            for (int i = tid; i < NHID / 4; i += RTPB) {
                dz[i] = szp[i];
                dh[i] = shp[i];
            }
        }
    }

    // per-row carry state: lane 0 owns row r0, lane 1 owns row r0+1
    float z_s = 0.f, ht_s = 0.f, h_s = 0.f, bzr = 0.f;
    int myrow = r0 + l;
    bool owner = (l < 2) && (myrow < NHID);
    if (owner) {
        z_s  = zt0[myrow];
        ht_s = htilde0[myrow];
        h_s  = hprev0[myrow];
        bzr  = bz[myrow];
        g_hp[0][myrow] = h_s;            // hp buffer 0 = hprev0
    }
    gbar(e0 + (++ec), b);

    const float4* u0z = (const float4*)(sU + (size_t)w * 4 * NHID);
    const float4* u0h = u0z + NHID / 4;
    const float4* u1z = u0h + NHID / 4;
    const float4* u1h = u1z + NHID / 4;

    for (int t = 0; t < T_STEPS; t++) {
        // full hp_t into registers via L2 (other SMs wrote it)
        const float4* hpg = (const float4*)(g_hp[t & 1]);
        float4 hp[16];
#pragma unroll
        for (int j = 0; j < 16; j++)
            hp[j] = __ldcg(hpg + l + 32 * j);

        float xzv = 0.f, xhv = 0.f;
        if (owner) {
            xzv = __ldg(&g_xz[(size_t)t * NHID + myrow]);
            xhv = __ldg(&g_xh[(size_t)t * NHID + myrow]);
        }

        // 4 dot products (2 rows x {z,h}) from SMEM-resident U
        float d0 = 0.f, d1 = 0.f, d2 = 0.f, d3 = 0.f;
#pragma unroll
        for (int j = 0; j < 16; j++) {
            float4 hv = hp[j];
            float4 a0 = u0z[l + 32 * j];
            d0 = fmaf(a0.x, hv.x, d0); d0 = fmaf(a0.y, hv.y, d0);
            d0 = fmaf(a0.z, hv.z, d0); d0 = fmaf(a0.w, hv.w, d0);
            float4 b0 = u0h[l + 32 * j];
            d1 = fmaf(b0.x, hv.x, d1); d1 = fmaf(b0.y, hv.y, d1);
            d1 = fmaf(b0.z, hv.z, d1); d1 = fmaf(b0.w, hv.w, d1);
            float4 a1 = u1z[l + 32 * j];
            d2 = fmaf(a1.x, hv.x, d2); d2 = fmaf(a1.y, hv.y, d2);
            d2 = fmaf(a1.z, hv.z, d2); d2 = fmaf(a1.w, hv.w, d2);
            float4 b1 = u1h[l + 32 * j];
            d3 = fmaf(b1.x, hv.x, d3); d3 = fmaf(b1.y, hv.y, d3);
            d3 = fmaf(b1.z, hv.z, d3); d3 = fmaf(b1.w, hv.w, d3);
        }
#pragma unroll
        for (int o = 16; o > 0; o >>= 1) {
            d0 += __shfl_xor_sync(0xffffffffu, d0, o);
            d1 += __shfl_xor_sync(0xffffffffu, d1, o);
            d2 += __shfl_xor_sync(0xffffffffu, d2, o);
            d3 += __shfl_xor_sync(0xffffffffu, d3, o);
        }

        if (owner) {
            float dz = (l == 0) ? d0 : d2;
            float dh = (l == 0) ? d1 : d3;
            // reference order: h uses STALE z/htilde from the previous step
            float h_new  = (1.0f - z_s) * h_s + z_s * ht_s;
            float z_new  = 1.0f / (1.0f + expf(-(xzv + dz + bzr)));
            float ht_new = tanhf(xhv + dh);
            g_hp[(t + 1) & 1][myrow] = h_new;
            z_s = z_new; ht_s = ht_new; h_s = h_new;
        }

        gbar(e0 + (++ec), b);
    }

    // final h_T lives in g_hp[0]; logits: warp gw = b*7 + w does one category
    {
        int gw = b * WARPS + w;
        if (gw < NCATS) {
            const float4* wo = (const float4*)(Wout + (size_t)gw * NHID);
            const float4* hf = (const float4*)(g_hp[0]);
            float s = 0.f;
#pragma unroll
            for (int j = 0; j < 16; j++) {
                float4 wv = __ldg(wo + l + 32 * j);
                float4 hv = __ldcg(hf + l + 32 * j);
                s = fmaf(wv.x, hv.x, s); s = fmaf(wv.y, hv.y, s);
                s = fmaf(wv.z, hv.z, s); s = fmaf(wv.w, hv.w, s);
            }
#pragma unroll
            for (int o = 16; o > 0; o >>= 1)
                s += __shfl_xor_sync(0xffffffffu, s, o);
            if (l == 0) g_logits[gw] = s;
        }
    }
    gbar(e0 + (++ec), b);

    // softmax over 1000 logits by block 0
    if (b == 0) {
        __shared__ float sred[WARPS];
        float m = -1e30f;
        for (int c = tid; c < NCATS; c += RTPB)
            m = fmaxf(m, __ldcg(&g_logits[c]));
#pragma unroll
        for (int o = 16; o > 0; o >>= 1)
            m = fmaxf(m, __shfl_xor_sync(0xffffffffu, m, o));
        if (l == 0) sred[w] = m;
        __syncthreads();
        if (tid < 32) {
            float mm = (tid < WARPS) ? sred[tid] : -1e30f;
#pragma unroll
            for (int o = 16; o > 0; o >>= 1)
                mm = fmaxf(mm, __shfl_xor_sync(0xffffffffu, mm, o));
            if (tid == 0) sred[0] = mm;
        }
        __syncthreads();
        float gmax = sred[0];
        __syncthreads();
        float s = 0.f;
        for (int c = tid; c < NCATS; c += RTPB)
            s += expf(__ldcg(&g_logits[c]) - gmax);
#pragma unroll
        for (int o = 16; o > 0; o >>= 1)
            s += __shfl_xor_sync(0xffffffffu, s, o);
        if (l == 0) sred[w] = s;
        __syncthreads();
        if (tid < 32) {
            float ss = (tid < WARPS) ? sred[tid] : 0.f;
#pragma unroll
            for (int o = 16; o > 0; o >>= 1)
                ss += __shfl_xor_sync(0xffffffffu, ss, o);
            if (tid == 0) sred[0] = ss;
        }
        __syncthreads();
        float inv = 1.0f / sred[0];
        for (int c = tid; c < NCATS; c += RTPB)
            out[c] = expf(__ldcg(&g_logits[c]) - gmax) * inv;
    }
}

// ---------------- launch ----------------
extern "C" void kernel_launch(void* const* d_in, const int* in_sizes, int n_in,
                              void* d_out, int out_size) {
    (void)in_sizes; (void)n_in; (void)out_size;
    const float* x    = (const float*)d_in[0];
    const float* Wh   = (const float*)d_in[1];
    const float* Wz   = (const float*)d_in[2];
    // d_in[3] = Wr : dead (rt never used)
    const float* Uh   = (const float*)d_in[4];
    const float* Uz   = (const float*)d_in[5];
    const float* bz   = (const float*)d_in[6];
    // d_in[7] = Ur, d_in[8] = br : dead
    const float* Wout = (const float*)d_in[9];
    // d_in[10] = h0 : dead (overwritten before first use)
    const float* zt0  = (const float*)d_in[11];
    const float* ht0  = (const float*)d_in[12];
    const float* hp0  = (const float*)d_in[13];
    float* out = (float*)d_out;

    const int smem = WARPS * 4 * NHID * (int)sizeof(float);  // 229376 B
    cudaFuncSetAttribute(recur_kernel,
                         cudaFuncAttributeMaxDynamicSharedMemorySize, smem);

    dim3 ggrid(NHID / BN, T_STEPS / BM, 2);
    gemm_xw_kernel<<<ggrid, 256>>>(x, Wz, Wh);
    recur_kernel<<<GBLK, RTPB, smem>>>(Uz, Uh, bz, zt0, ht0, hp0, Wout, out);
}

// round 13
// speedup vs baseline: 1.5022x; 1.3237x over previous
#include <cuda_runtime.h>
#include <math.h>

// Problem dims
#define T_STEPS 1024
#define D_DIM   2048
#define NHID    2048
#define NCATS   1000

// Recurrence config: 148 persistent blocks, 14 warps (448 thr).
// Row-pair p in [0,7): rows b*14+2p, b*14+2p+1. Warps 2p (K-half 0) and
// 2p+1 (K-half 1) co-compute the pair's 4 dots; partials combined in SMEM.
#define GBLK    148
#define WARPS   14
#define RTPB    448
#define RPB     14
#define HBUF    4          // hp ring buffers (needed for 1-barrier-per-2-steps)

// ---------------- device scratch (no allocations allowed) ----------------
__device__ float    g_xz[T_STEPS * NHID];   // x @ Wz.T
__device__ float    g_xh[T_STEPS * NHID];   // x @ Wh.T
__device__ float    g_hp[HBUF][NHID];       // hp ring
__device__ float    g_logits[NCATS];
// Barrier state (R11-proven): 4 group counters on distinct L2 lines, root,
// single epoch word.
__device__ unsigned g_cnt4[128];
__device__ unsigned g_rootpad[32];
__device__ unsigned g_epochpad[32];

// ---------------- grid barrier (identical to R11's passing version) ------
__device__ __forceinline__ void gbar(unsigned target, int bid) {
    __syncthreads();
    if (threadIdx.x == 0) {
        __threadfence();
        unsigned old = atomicAdd(&g_cnt4[(bid & 3) * 32], 1u);
        if (old % 37u == 36u) {                       // last arrival in group
            unsigned r = atomicAdd(&g_rootpad[0], 1u);
            if ((r & 3u) == 3u)                       // last group
                atomicExch(&g_epochpad[0], target);
        }
        while ((int)(*(volatile unsigned*)&g_epochpad[0] - target) < 0) {
            __nanosleep(32);
        }
        __threadfence();
    }
    __syncthreads();
}

__device__ __forceinline__ void st_cg(float* p, float v) {
    asm volatile("st.global.cg.f32 [%0], %1;" :: "l"(p), "f"(v) : "memory");
}

// ---------------- fused input projections (unchanged, proven) ------------
#define BM 128
#define BN 128
#define BK 16

__global__ __launch_bounds__(256, 2)
void gemm_xw_kernel(const float* __restrict__ x,
                    const float* __restrict__ Wz,
                    const float* __restrict__ Wh) {
    const float* W = (blockIdx.z == 0) ? Wz : Wh;
    float* C       = (blockIdx.z == 0) ? g_xz : g_xh;

    __shared__ float As[BK][BM];
    __shared__ float Bs[BK][BN];

    const int tid = threadIdx.x;
    const int m0  = blockIdx.y * BM;
    const int n0  = blockIdx.x * BN;
    const int tr  = tid >> 4;
    const int tc  = tid & 15;

    float acc[8][8];
#pragma unroll
    for (int i = 0; i < 8; i++)
#pragma unroll
        for (int j = 0; j < 8; j++) acc[i][j] = 0.0f;

    for (int k0 = 0; k0 < D_DIM; k0 += BK) {
#pragma unroll
        for (int r = 0; r < 2; r++) {
            int idx = tid + r * 256;
            int row = idx >> 2;
            int c4  = (idx & 3) << 2;
            float4 a = *(const float4*)(x + (size_t)(m0 + row) * D_DIM + k0 + c4);
            As[c4 + 0][row] = a.x; As[c4 + 1][row] = a.y;
            As[c4 + 2][row] = a.z; As[c4 + 3][row] = a.w;
            float4 b = *(const float4*)(W + (size_t)(n0 + row) * D_DIM + k0 + c4);
            Bs[c4 + 0][row] = b.x; Bs[c4 + 1][row] = b.y;
            Bs[c4 + 2][row] = b.z; Bs[c4 + 3][row] = b.w;
        }
        __syncthreads();
#pragma unroll
        for (int kk = 0; kk < BK; kk++) {
            float ra[8], rb[8];
            *(float4*)&ra[0] = *(const float4*)&As[kk][tr * 4];
            *(float4*)&ra[4] = *(const float4*)&As[kk][64 + tr * 4];
            *(float4*)&rb[0] = *(const float4*)&Bs[kk][tc * 4];
            *(float4*)&rb[4] = *(const float4*)&Bs[kk][64 + tc * 4];
#pragma unroll
            for (int i = 0; i < 8; i++)
#pragma unroll
                for (int j = 0; j < 8; j++)
                    acc[i][j] = fmaf(ra[i], rb[j], acc[i][j]);
        }
        __syncthreads();
    }

#pragma unroll
    for (int hi = 0; hi < 2; hi++)
#pragma unroll
        for (int i = 0; i < 4; i++) {
            int row = m0 + hi * 64 + tr * 4 + i;
#pragma unroll
            for (int hj = 0; hj < 2; hj++) {
                float4 v;
                v.x = acc[hi * 4 + i][hj * 4 + 0];
                v.y = acc[hi * 4 + i][hj * 4 + 1];
                v.z = acc[hi * 4 + i][hj * 4 + 2];
                v.w = acc[hi * 4 + i][hj * 4 + 3];
                *(float4*)(C + (size_t)row * NHID + n0 + hj * 64 + tc * 4) = v;
            }
        }
}

// ---------------- persistent recurrence + classifier + softmax ------------
// SMEM U layout (float4 units): warp w gets 1024 float4 = 4 rows x 256:
//   m=0: Uz[rp0], m=1: Uh[rp0], m=2: Uz[rp1], m=3: Uh[rp1],
//   each holding K-half q = w&1 (elements [q*1024, q*1024+1024)).
__global__ __launch_bounds__(RTPB, 1)
void recur_kernel(const float* __restrict__ Uz,
                  const float* __restrict__ Uh,
                  const float* __restrict__ bz,
                  const float* __restrict__ zt0,
                  const float* __restrict__ htilde0,
                  const float* __restrict__ hprev0,
                  const float* __restrict__ Wout,
                  float* __restrict__ out) {
    extern __shared__ float sU[];        // 14 * 4 * 1024 floats = 229376 B
    __shared__ float sred4[2][WARPS][4]; // partial-dot exchange, double-buffered
    __shared__ float sredW[WARPS];       // softmax scratch

    const int b   = blockIdx.x;
    const int tid = threadIdx.x;
    const int w   = tid >> 5;
    const int l   = tid & 31;
    const int p   = w >> 1;              // pair index 0..6
    const int q   = w & 1;               // K-half
    const int r0  = b * RPB + 2 * p;     // pair's first row

    // Epoch base: read before this block's first arrival (R11-proven).
    unsigned e0 = *(volatile unsigned*)&g_epochpad[0];
    unsigned ec = 0;

    // one-time: load U slices into SMEM. 56 segments of 256 float4 each.
    for (int idx = tid; idx < WARPS * 4 * 256; idx += RTPB) {
        int seg = idx >> 8;              // 0..55
        int off = idx & 255;
        int wp  = seg >> 2;              // dest warp 0..13
        int m   = seg & 3;
        int pp  = wp >> 1, qq = wp & 1;
        int r   = b * RPB + 2 * pp + (m >> 1);
        if (r < NHID) {
            const float* src = ((m & 1) ? Uh : Uz) + (size_t)r * NHID + qq * 1024;
            ((float4*)sU)[wp * 1024 + m * 256 + off] = *(const float4*)(src + off * 4);
        }
    }

    // Owner state: even warps (q==0), lanes 0/1 own rows r0, r0+1.
    int  myrow = r0 + l;
    bool owner = (q == 0) && (l < 2) && (myrow < NHID);
    float z_s = 0.f, ht_s = 0.f, h_s = 0.f, bzr = 0.f;
    if (owner) {
        z_s  = zt0[myrow];
        ht_s = htilde0[myrow];
        h_s  = hprev0[myrow];
        bzr  = bz[myrow];
        g_hp[0][myrow] = h_s;            // hp_0 = hprev0
    }
    gbar(e0 + (++ec), b);

    const float4* uw = ((const float4*)sU) + (size_t)w * 1024;

    // Iterations t = 0..1022 do dots; the final h (= h_new_1023, reference
    // discards the last step's gates) is stored after the loop.
    for (int t = 0; t < T_STEPS - 1; t++) {
        // TOP store: hp_{t+1} from STALE state (needs no dots this step).
        if (owner) {
            float h_new = (1.0f - z_s) * h_s + z_s * ht_s;
            st_cg(&g_hp[(t + 1) & 3][myrow], h_new);
            h_s = h_new;
        }
        // One grid barrier per TWO steps (flow/anti-deps proven with HBUF=4).
        if ((t & 1) == 0) gbar(e0 + (++ec), b);

        // This warp's K-half of hp_t.
        const float4* hpg = ((const float4*)g_hp[t & 3]) + q * 256;
        float4 hp[8];
#pragma unroll
        for (int j = 0; j < 8; j++)
            hp[j] = __ldcg(hpg + l + 32 * j);

        float xzv = 0.f, xhv = 0.f;
        if (owner) {
            xzv = __ldg(&g_xz[(size_t)t * NHID + myrow]);
            xhv = __ldg(&g_xh[(size_t)t * NHID + myrow]);
        }

        // 4 partial dots over this K-half.
        float d0 = 0.f, d1 = 0.f, d2 = 0.f, d3 = 0.f;
#pragma unroll
        for (int j = 0; j < 8; j++) {
            float4 hv = hp[j];
            float4 a0 = uw[0 * 256 + l + 32 * j];
            d0 = fmaf(a0.x, hv.x, d0); d0 = fmaf(a0.y, hv.y, d0);
            d0 = fmaf(a0.z, hv.z, d0); d0 = fmaf(a0.w, hv.w, d0);
            float4 a1 = uw[1 * 256 + l + 32 * j];
            d1 = fmaf(a1.x, hv.x, d1); d1 = fmaf(a1.y, hv.y, d1);
            d1 = fmaf(a1.z, hv.z, d1); d1 = fmaf(a1.w, hv.w, d1);
            float4 a2 = uw[2 * 256 + l + 32 * j];
            d2 = fmaf(a2.x, hv.x, d2); d2 = fmaf(a2.y, hv.y, d2);
            d2 = fmaf(a2.z, hv.z, d2); d2 = fmaf(a2.w, hv.w, d2);
            float4 a3 = uw[3 * 256 + l + 32 * j];
            d3 = fmaf(a3.x, hv.x, d3); d3 = fmaf(a3.y, hv.y, d3);
            d3 = fmaf(a3.z, hv.z, d3); d3 = fmaf(a3.w, hv.w, d3);
        }
#pragma unroll
        for (int o = 16; o > 0; o >>= 1) {
            d0 += __shfl_xor_sync(0xffffffffu, d0, o);
            d1 += __shfl_xor_sync(0xffffffffu, d1, o);
            d2 += __shfl_xor_sync(0xffffffffu, d2, o);
            d3 += __shfl_xor_sync(0xffffffffu, d3, o);
        }

        // Exchange partials across the warp pair.
        if (l == 0) {
            float4 v; v.x = d0; v.y = d1; v.z = d2; v.w = d3;
            *(float4*)&sred4[t & 1][w][0] = v;
        }
        __syncthreads();

        if (owner) {
            // partial order: [dz(rp0), dh(rp0), dz(rp1), dh(rp1)]
            float dz = sred4[t & 1][2 * p][2 * l + 0] + sred4[t & 1][2 * p + 1][2 * l + 0];
            float dh = sred4[t & 1][2 * p][2 * l + 1] + sred4[t & 1][2 * p + 1][2 * l + 1];
            z_s  = 1.0f / (1.0f + expf(-(xzv + dz + bzr)));
            ht_s = tanhf(xhv + dh);
        }
    }

    // Final h = h_new_{1023} (uses step-1022 gates; last step's dots are dead).
    if (owner) {
        float h_new = (1.0f - z_s) * h_s + z_s * ht_s;
        st_cg(&g_hp[T_STEPS & 3][myrow], h_new);   // g_hp[0]
    }
    gbar(e0 + (++ec), b);

    // logits: warp gw = b*14 + w computes one category.
    {
        int gw = b * WARPS + w;
        if (gw < NCATS) {
            const float4* wo = (const float4*)(Wout + (size_t)gw * NHID);
            const float4* hf = (const float4*)(g_hp[0]);
            float s = 0.f;
#pragma unroll
            for (int j = 0; j < 16; j++) {
                float4 wv = __ldg(wo + l + 32 * j);
                float4 hv = __ldcg(hf + l + 32 * j);
                s = fmaf(wv.x, hv.x, s); s = fmaf(wv.y, hv.y, s);
                s = fmaf(wv.z, hv.z, s); s = fmaf(wv.w, hv.w, s);
            }
#pragma unroll
            for (int o = 16; o > 0; o >>= 1)
                s += __shfl_xor_sync(0xffffffffu, s, o);
            if (l == 0) g_logits[gw] = s;
        }
    }
    gbar(e0 + (++ec), b);

    // softmax over 1000 logits by block 0
    if (b == 0) {
        float m = -1e30f;
        for (int c = tid; c < NCATS; c += RTPB)
            m = fmaxf(m, __ldcg(&g_logits[c]));
#pragma unroll
        for (int o = 16; o > 0; o >>= 1)
            m = fmaxf(m, __shfl_xor_sync(0xffffffffu, m, o));
        if (l == 0) sredW[w] = m;
        __syncthreads();
        if (tid < 32) {
            float mm = (tid < WARPS) ? sredW[tid] : -1e30f;
#pragma unroll
            for (int o = 16; o > 0; o >>= 1)
                mm = fmaxf(mm, __shfl_xor_sync(0xffffffffu, mm, o));
            if (tid == 0) sredW[0] = mm;
        }
        __syncthreads();
        float gmax = sredW[0];
        __syncthreads();
        float s = 0.f;
        for (int c = tid; c < NCATS; c += RTPB)
            s += expf(__ldcg(&g_logits[c]) - gmax);
#pragma unroll
        for (int o = 16; o > 0; o >>= 1)
            s += __shfl_xor_sync(0xffffffffu, s, o);
        if (l == 0) sredW[w] = s;
        __syncthreads();
        if (tid < 32) {
            float ss = (tid < WARPS) ? sredW[tid] : 0.f;
#pragma unroll
            for (int o = 16; o > 0; o >>= 1)
                ss += __shfl_xor_sync(0xffffffffu, ss, o);
            if (tid == 0) sredW[0] = ss;
        }
        __syncthreads();
        float inv = 1.0f / sredW[0];
        for (int c = tid; c < NCATS; c += RTPB)
            out[c] = expf(__ldcg(&g_logits[c]) - gmax) * inv;
    }
}

// ---------------- launch ----------------
extern "C" void kernel_launch(void* const* d_in, const int* in_sizes, int n_in,
                              void* d_out, int out_size) {
    (void)in_sizes; (void)n_in; (void)out_size;
    const float* x    = (const float*)d_in[0];
    const float* Wh   = (const float*)d_in[1];
    const float* Wz   = (const float*)d_in[2];
    // d_in[3] = Wr : dead (rt never used)
    const float* Uh   = (const float*)d_in[4];
    const float* Uz   = (const float*)d_in[5];
    const float* bz   = (const float*)d_in[6];
    // d_in[7] = Ur, d_in[8] = br : dead
    const float* Wout = (const float*)d_in[9];
    // d_in[10] = h0 : dead (overwritten before first use)
    const float* zt0  = (const float*)d_in[11];
    const float* ht0  = (const float*)d_in[12];
    const float* hp0  = (const float*)d_in[13];
    float* out = (float*)d_out;

    const int smem = WARPS * 4 * 1024 * (int)sizeof(float);  // 229376 B
    cudaFuncSetAttribute(recur_kernel,
                         cudaFuncAttributeMaxDynamicSharedMemorySize, smem);

    dim3 ggrid(NHID / BN, T_STEPS / BM, 2);
    gemm_xw_kernel<<<ggrid, 256>>>(x, Wz, Wh);
    recur_kernel<<<GBLK, RTPB, smem>>>(Uz, Uh, bz, zt0, ht0, hp0, Wout, out);
}